// round 14
// baseline (speedup 1.0000x reference)
#include <cuda_runtime.h>
#include <cuda_fp16.h>
#include <math.h>
#include <stdint.h>

#define BB 4
#define TT 2048
#define HH 16
#define DD 64
#define CC (HH*DD)      // 1024
#define MM (BB*TT)      // 8192
#define GK 1024         // K of all GEMMs

// ---------------- scratch (device globals; no allocation allowed) ----------
__device__ __align__(256) float g_cos[TT * 32];
__device__ __align__(256) float g_sin[TT * 32];

__device__ __align__(256) __half g_x16[(size_t)MM * GK];
__device__ __align__(256) __half g_y16[(size_t)MM * GK];
__device__ __align__(256) __half g_q16[(size_t)BB*HH*TT*DD];
__device__ __align__(256) __half g_k16[(size_t)BB*HH*TT*DD];
__device__ __align__(256) __half g_vt16[(size_t)BB*HH*TT*DD];
// weights transposed [N,K], single fp16
__device__ __align__(256) __half g_wh[(size_t)3 * CC * GK];
__device__ __align__(256) __half g_wch[(size_t)CC * GK];

// ---------------- helpers ----------------------------------------------------
__device__ __forceinline__ uint32_t smem_u32(const void* p) {
    return (uint32_t)__cvta_generic_to_shared(p);
}

__device__ __forceinline__ void cp_async16(uint32_t saddr, const void* gaddr) {
    asm volatile("cp.async.cg.shared.global [%0], [%1], 16;" :: "r"(saddr), "l"(gaddr) : "memory");
}

__device__ __forceinline__ void ldsm_x4(uint32_t& r0, uint32_t& r1, uint32_t& r2, uint32_t& r3,
                                        uint32_t addr) {
    asm volatile("ldmatrix.sync.aligned.m8n8.x4.shared.b16 {%0,%1,%2,%3}, [%4];"
                 : "=r"(r0), "=r"(r1), "=r"(r2), "=r"(r3) : "r"(addr));
}

__device__ __forceinline__ void mma16816(float& c0, float& c1, float& c2, float& c3,
                                         uint32_t a0, uint32_t a1, uint32_t a2, uint32_t a3,
                                         uint32_t b0, uint32_t b1) {
    asm volatile(
        "mma.sync.aligned.m16n8k16.row.col.f32.f16.f16.f32 "
        "{%0,%1,%2,%3}, {%4,%5,%6,%7}, {%8,%9}, {%0,%1,%2,%3};"
        : "+f"(c0), "+f"(c1), "+f"(c2), "+f"(c3)
        : "r"(a0), "r"(a1), "r"(a2), "r"(a3), "r"(b0), "r"(b1));
}

__device__ __forceinline__ uint32_t pack_h16(float a, float b) {
    __half2 t = __floats2half2_rn(a, b);
    return *reinterpret_cast<uint32_t*>(&t);
}

__device__ __forceinline__ void store_h2(__half* dst, size_t off, float a, float b) {
    *reinterpret_cast<__half2*>(dst + off) = __floats2half2_rn(a, b);
}

// ---------------- HMMA GEMM: C = A16 @ B16^T (single fp16) -----------------
// 128x128 CTA tile, 8 warps (2m x 4n), warp tile 64x32, BK=64, 3-stage
// cp.async pipeline, ONE barrier per k-chunk, 128B rows w/ j^(r&7) swizzle,
// 2 CTAs/SM.
#define BK 64
#define NUMK (GK / BK)          // 16
#define ROWB 128                // 128B data (64 fp16), swizzled
#define TILE_B (128 * ROWB)     // 16384
#define STAGE_B (2 * TILE_B)    // 32768 (A, B)
#define SMEM_DYN (3 * STAGE_B)  // 98304 -> 2 CTAs/SM

__global__ void __launch_bounds__(256, 2)
gemm_kernel_mma(const __half* __restrict__ A16, const __half* __restrict__ B16,
                float* __restrict__ Cm, int Ndim, int mode,
                const float* __restrict__ gcos, const float* __restrict__ gsin,
                __half* __restrict__ q16, __half* __restrict__ k16,
                __half* __restrict__ vt16)
{
    extern __shared__ char smem_raw[];
    const uint32_t sbase = smem_u32(smem_raw);

    const int tid  = threadIdx.x;
    const int lane = tid & 31;
    const int warp = tid >> 5;
    const int mw   = warp & 1;
    const int nw   = warp >> 1;
    const int m0 = blockIdx.y * 128;
    const int n0 = blockIdx.x * 128;

    auto prefetch = [&](int kc) {
        const uint32_t sstage = sbase + (uint32_t)(kc % 3) * STAGE_B;
        #pragma unroll
        for (int i = 0; i < 8; i++) {
            const int c = i * 256 + tid;        // 0..2047
            const int tile = c >> 10;           // 0=A 1=B
            const int r = (c >> 3) & 127;
            const int j = c & 7;
            const __half* g = (tile == 0)
                ? A16 + (size_t)(m0 + r) * GK + kc * BK + j * 8
                : B16 + (size_t)(n0 + r) * GK + kc * BK + j * 8;
            cp_async16(sstage + tile * TILE_B + r * ROWB + ((j ^ (r & 7)) << 4), g);
        }
    };

    prefetch(0);
    asm volatile("cp.async.commit_group;" ::: "memory");
    prefetch(1);
    asm volatile("cp.async.commit_group;" ::: "memory");

    const uint32_t aRowBase = (uint32_t)((mw * 64 + (lane & 15)) * ROWB);
    const uint32_t xa = (lane & 15) & 7;
    const uint32_t bRowBase = (uint32_t)((nw * 32 + (lane & 7) + ((lane >> 4) << 3)) * ROWB);
    const uint32_t xb = lane & 7;
    const uint32_t aHalf = (lane >> 4);
    const uint32_t bHalf = ((lane >> 3) & 1);

    float acc[4][4][4];
    #pragma unroll
    for (int mt = 0; mt < 4; mt++)
        #pragma unroll
        for (int nt = 0; nt < 4; nt++)
            #pragma unroll
            for (int e = 0; e < 4; e++) acc[mt][nt][e] = 0.f;

    for (int kc = 0; kc < NUMK; kc++) {
        asm volatile("cp.async.wait_group 1;" ::: "memory");
        __syncthreads();

        const uint32_t sstage = sbase + (uint32_t)(kc % 3) * STAGE_B;
        const uint32_t aTile = sstage;
        const uint32_t bTile = sstage + TILE_B;

        #pragma unroll
        for (int ks = 0; ks < 4; ks++) {
            const uint32_t aOff = ((uint32_t)(ks * 2 + aHalf) ^ xa) << 4;
            const uint32_t bOff = ((uint32_t)(ks * 2 + bHalf) ^ xb) << 4;
            uint32_t bh[4][2];
            #pragma unroll
            for (int np = 0; np < 2; np++) {
                const uint32_t off = bRowBase + np * (16 * ROWB) + bOff;
                ldsm_x4(bh[np*2][0], bh[np*2][1], bh[np*2+1][0], bh[np*2+1][1], bTile + off);
            }
            #pragma unroll
            for (int mt = 0; mt < 4; mt++) {
                uint32_t ah[4];
                const uint32_t off = aRowBase + mt * (16 * ROWB) + aOff;
                ldsm_x4(ah[0], ah[1], ah[2], ah[3], aTile + off);
                #pragma unroll
                for (int nt = 0; nt < 4; nt++) {
                    float* c = acc[mt][nt];
                    mma16816(c[0], c[1], c[2], c[3],
                             ah[0], ah[1], ah[2], ah[3], bh[nt][0], bh[nt][1]);
                }
            }
        }
        if (kc + 2 < NUMK) prefetch(kc + 2);
        asm volatile("cp.async.commit_group;" ::: "memory");
    }

    if (mode == 0) {
        const int rbase = m0 + mw * 64 + (lane >> 2);
        const int cbase = n0 + nw * 32 + ((lane & 3) << 1);
        #pragma unroll
        for (int mt = 0; mt < 4; mt++) {
            #pragma unroll
            for (int nt = 0; nt < 4; nt++) {
                float* c = acc[mt][nt];
                float* p0 = Cm + (size_t)(rbase + mt * 16) * Ndim + cbase + nt * 8;
                float* p1 = p0 + (size_t)8 * Ndim;
                *reinterpret_cast<float2*>(p0) = make_float2(c[0], c[1]);
                *reinterpret_cast<float2*>(p1) = make_float2(c[2], c[3]);
            }
        }
        return;
    }

    // ---- fused QKV epilogue: stage fp32 tile in smem [128][132] ----
    float* sm = reinterpret_cast<float*>(smem_raw);
    __syncthreads();
    const int rloc = mw * 64 + (lane >> 2);
    const int cloc = nw * 32 + ((lane & 3) << 1);
    #pragma unroll
    for (int mt = 0; mt < 4; mt++) {
        #pragma unroll
        for (int nt = 0; nt < 4; nt++) {
            float* c = acc[mt][nt];
            float* p0 = sm + (size_t)(rloc + mt * 16) * 132 + cloc + nt * 8;
            *reinterpret_cast<float2*>(p0)           = make_float2(c[0], c[1]);
            *reinterpret_cast<float2*>(p0 + 8 * 132) = make_float2(c[2], c[3]);
        }
    }
    __syncthreads();

    const int ct = blockIdx.x;
    const int b = m0 >> 11;
    const int t_base = m0 & (TT - 1);

    if (ct < 16) {
        const bool isQ = (ct < 8);
        // Q scale folds 1/sqrt(D) AND log2(e): flash softmax runs in exp2 domain
        const float qs = isQ ? (0.125f * 1.4426950408889634f) : 1.0f;
        __half* dst = isQ ? q16 : k16;
        const int hbase = (isQ ? ct : (ct - 8)) * 2;
        #pragma unroll
        for (int i = 0; i < 16; i++) {
            const int idx = i * 256 + tid;
            const int dp = (idx & 15) * 2;
            const int hs = (idx >> 4) & 1;
            const int r  = idx >> 5;
            const int t  = t_base + r;
            const float c0 = gcos[t * 32 + dp],  c1 = gcos[t * 32 + dp + 1];
            const float s0 = gsin[t * 32 + dp],  s1 = gsin[t * 32 + dp + 1];
            const float* row = sm + (size_t)r * 132 + hs * 64;
            const float x1 = row[dp],      x1b = row[dp + 1];
            const float x2 = row[dp + 32], x2b = row[dp + 33];
            const float o0 = (x1 * c0 - x2 * s0) * qs;
            const float o1 = (x1b * c1 - x2b * s1) * qs;
            const float o2 = (x2 * c0 + x1 * s0) * qs;
            const float o3 = (x2b * c1 + x1b * s1) * qs;
            const size_t base = (((size_t)b * HH + hbase + hs) * TT + t) * 64;
            store_h2(dst, base + dp, o0, o1);
            store_h2(dst, base + dp + 32, o2, o3);
        }
    } else {
        const int hbase = (ct - 16) * 2;
        #pragma unroll
        for (int i = 0; i < 32; i++) {
            const int idx = i * 256 + tid;
            const int c  = idx >> 6;
            const int t2 = idx & 63;
            const int hs = c >> 6;
            const int d  = c & 63;
            const float a  = sm[(size_t)(2 * t2) * 132 + c];
            const float bv = sm[(size_t)(2 * t2 + 1) * 132 + c];
            const int t = t_base + 2 * t2;
            store_h2(vt16, (((size_t)b * HH + hbase + hs) * 64 + d) * TT + t, a, bv);
        }
    }
}

// ---------------- fp32 -> fp16 convert -------------------------------------
__global__ void split_kernel(const float4* __restrict__ in, uint2* __restrict__ out, int n4)
{
    int i = blockIdx.x * blockDim.x + threadIdx.x;
    if (i >= n4) return;
    float4 v = in[i];
    __half2 a = __floats2half2_rn(v.x, v.y);
    __half2 b = __floats2half2_rn(v.z, v.w);
    uint2 o;
    o.x = *reinterpret_cast<uint32_t*>(&a);
    o.y = *reinterpret_cast<uint32_t*>(&b);
    out[i] = o;
}

// -------- combined W transpose (single fp16) + RoPE table ------------------
__global__ void transpose_split_all(const float* __restrict__ Wq,
                                    const float* __restrict__ Wkv,
                                    const float* __restrict__ Wc,
                                    __half* __restrict__ wh, __half* __restrict__ wch,
                                    float* __restrict__ gcos, float* __restrict__ gsin)
{
    const int tx = threadIdx.x, ty = threadIdx.y;
    if (blockIdx.y == 32) {
        const int tid = ty * 32 + tx;
        #pragma unroll
        for (int e = 0; e < 2; e++) {
            int i = blockIdx.x * 512 + e * 256 + tid;
            int t = i >> 5;
            int d = i & 31;
            float inv = (float)exp(-((double)(2 * d) / 64.0) * log(10000.0));
            float ang = (float)t * inv;
            gcos[i] = cosf(ang);
            gsin[i] = sinf(ang);
        }
        return;
    }

    __shared__ float t[32][33];
    const int nx = blockIdx.x;
    const int k0 = blockIdx.y * 32;
    const float* W;
    __half* Th;
    int N, n0;
    if (nx < 32)       { W = Wq;  N = CC;     n0 = nx * 32;        Th = wh; }
    else if (nx < 96)  { W = Wkv; N = 2 * CC; n0 = (nx - 32) * 32;
                         Th = wh + (size_t)CC * GK; }
    else               { W = Wc;  N = CC;     n0 = (nx - 96) * 32; Th = wch; }

    #pragma unroll
    for (int i = 0; i < 32; i += 8)
        t[ty + i][tx] = W[(size_t)(k0 + ty + i) * N + n0 + tx];
    __syncthreads();
    #pragma unroll
    for (int i = 0; i < 32; i += 8) {
        float v = t[tx][ty + i];
        Th[(size_t)(n0 + ty + i) * GK + k0 + tx] = __float2half_rn(v);
    }
}

// ---------------- Flash attention, fp16 HMMA, exp2-domain softmax ----------
#define FROWB 144
#define FQ_TILE (128 * FROWB)        // 18432
#define FK_TILE (64 * FROWB)         // 9216
#define FV_TILE (64 * FROWB)         // 9216
#define FSTAGE (FK_TILE + FV_TILE)   // 18432
#define FSMEM (FQ_TILE + 3 * FSTAGE) // 73728 -> 2 CTAs/SM

__global__ void __launch_bounds__(256, 2)
flash_mma_kernel(const __half* __restrict__ q16, const __half* __restrict__ k16,
                 const __half* __restrict__ vt16, __half* __restrict__ y16)
{
    extern __shared__ char smem_raw[];
    const uint32_t sQ  = smem_u32(smem_raw);
    const uint32_t sKV = sQ + FQ_TILE;

    const int tid = threadIdx.x, lane = tid & 31, warp = tid >> 5;
    const int t0 = (gridDim.x - 1 - blockIdx.x) * 128;   // heavy-first
    const int h = blockIdx.y, b = blockIdx.z;
    const size_t bh = (size_t)b * HH + h;
    const int nkv = t0 / 64 + 2;

    #pragma unroll
    for (int i = 0; i < 4; i++) {
        int idx = i * 256 + tid;
        int r = idx >> 3, j = idx & 7;
        cp_async16(sQ + r * FROWB + j * 16, q16 + (bh * TT + t0 + r) * 64 + j * 8);
    }
    auto pref_kv = [&](int n) {
        const uint32_t sb = sKV + (uint32_t)(n % 3) * FSTAGE;
        const int j0 = n * 64;
        #pragma unroll
        for (int i = 0; i < 4; i++) {
            int idx = i * 256 + tid;
            int arr = idx >> 9, r = (idx >> 3) & 63, j = idx & 7;
            const __half* g = arr ? (vt16 + (bh * 64 + r) * TT + j0 + j * 8)
                                  : (k16 + (bh * TT + j0 + r) * 64 + j * 8);
            cp_async16(sb + arr * FK_TILE + r * FROWB + j * 16, g);
        }
    };
    pref_kv(0);
    asm volatile("cp.async.commit_group;" ::: "memory");
    pref_kv(1);
    asm volatile("cp.async.commit_group;" ::: "memory");

    const int wrow = t0 + warp * 16;
    const int gr = lane >> 2;
    const int qk = (lane & 3) * 2;
    const int row0 = wrow + gr;
    const int row1 = row0 + 8;

    uint32_t qa[4][4];
    float O[8][4];
    #pragma unroll
    for (int nt = 0; nt < 8; nt++)
        #pragma unroll
        for (int e = 0; e < 4; e++) O[nt][e] = 0.f;
    float mA = -1e30f, mB = -1e30f, lA = 0.f, lB = 0.f;

    const uint32_t bBaseOff = ((lane & 7) + ((lane >> 4) << 3)) * FROWB + (((lane >> 3) & 1) << 4);

    for (int n = 0; n < nkv; n++) {
        asm volatile("cp.async.wait_group 1;" ::: "memory");
        __syncthreads();

        if (n == 0) {
            const uint32_t qb = sQ + (warp * 16 + (lane & 15)) * FROWB + ((lane >> 4) << 4);
            #pragma unroll
            for (int ks = 0; ks < 4; ks++)
                ldsm_x4(qa[ks][0], qa[ks][1], qa[ks][2], qa[ks][3], qb + ks * 32);
        }

        const int j0 = n * 64;
        if (j0 <= wrow + 15) {
            const uint32_t sb = sKV + (uint32_t)(n % 3) * FSTAGE;
            float S[8][4];
            #pragma unroll
            for (int nt = 0; nt < 8; nt++)
                #pragma unroll
                for (int e = 0; e < 4; e++) S[nt][e] = 0.f;

            // ---- S = Q K^T (skip fully-masked nt subtiles, warp-uniform) ----
            #pragma unroll
            for (int ks = 0; ks < 4; ks++) {
                uint32_t B0[8], B1[8];
                #pragma unroll
                for (int q2 = 0; q2 < 4; q2++) {
                    if (j0 + q2 * 16 <= wrow + 15) {
                        const uint32_t off = bBaseOff + q2 * (16 * FROWB) + ks * 32;
                        ldsm_x4(B0[q2*2], B1[q2*2], B0[q2*2+1], B1[q2*2+1], sb + off);
                    }
                }
                #pragma unroll
                for (int nt = 0; nt < 8; nt++) {
                    if (j0 + nt * 8 <= wrow + 15) {
                        float* c = S[nt];
                        mma16816(c[0], c[1], c[2], c[3],
                                 qa[ks][0], qa[ks][1], qa[ks][2], qa[ks][3], B0[nt], B1[nt]);
                    }
                }
            }

            // ---- causal mask ----
            if (j0 + 63 > wrow) {
                #pragma unroll
                for (int nt = 0; nt < 8; nt++) {
                    const int c0 = j0 + nt * 8 + qk;
                    if (c0 > row0)     S[nt][0] = -1e30f;
                    if (c0 + 1 > row0) S[nt][1] = -1e30f;
                    if (c0 > row1)     S[nt][2] = -1e30f;
                    if (c0 + 1 > row1) S[nt][3] = -1e30f;
                }
            }

            // ---- online softmax (exp2 domain) ----
            float tmA = -1e30f, tmB = -1e30f;
            #pragma unroll
            for (int nt = 0; nt < 8; nt++) {
                tmA = fmaxf(tmA, fmaxf(S[nt][0], S[nt][1]));
                tmB = fmaxf(tmB, fmaxf(S[nt][2], S[nt][3]));
            }
            tmA = fmaxf(tmA, __shfl_xor_sync(0xffffffffu, tmA, 1));
            tmA = fmaxf(tmA, __shfl_xor_sync(0xffffffffu, tmA, 2));
            tmB = fmaxf(tmB, __shfl_xor_sync(0xffffffffu, tmB, 1));
            tmB = fmaxf(tmB, __shfl_xor_sync(0xffffffffu, tmB, 2));

            if (__any_sync(0xffffffffu, (tmA > mA) || (tmB > mB))) {
                const float mnA = fmaxf(mA, tmA), mnB = fmaxf(mB, tmB);
                const float aA = exp2f(mA - mnA), aB = exp2f(mB - mnB);
                lA *= aA; lB *= aB;
                #pragma unroll
                for (int nt = 0; nt < 8; nt++) {
                    O[nt][0] *= aA; O[nt][1] *= aA;
                    O[nt][2] *= aB; O[nt][3] *= aB;
                }
                mA = mnA; mB = mnB;
            }

            float sumA = 0.f, sumB = 0.f;
            #pragma unroll
            for (int nt = 0; nt < 8; nt++) {
                S[nt][0] = exp2f(S[nt][0] - mA);
                S[nt][1] = exp2f(S[nt][1] - mA);
                S[nt][2] = exp2f(S[nt][2] - mB);
                S[nt][3] = exp2f(S[nt][3] - mB);
                sumA += S[nt][0] + S[nt][1];
                sumB += S[nt][2] + S[nt][3];
            }
            lA += sumA;
            lB += sumB;

            // ---- O += P V (skip fully-masked ks blocks, warp-uniform) ----
            const uint32_t vb = sb + FK_TILE;
            #pragma unroll
            for (int ks = 0; ks < 4; ks++) {
                if (j0 + ks * 16 > wrow + 15) continue;   // P == 0 there
                const int n0t = 2 * ks, n1t = 2 * ks + 1;
                uint32_t pa[4];
                pa[0] = pack_h16(S[n0t][0], S[n0t][1]);
                pa[1] = pack_h16(S[n0t][2], S[n0t][3]);
                pa[2] = pack_h16(S[n1t][0], S[n1t][1]);
                pa[3] = pack_h16(S[n1t][2], S[n1t][3]);
                uint32_t V0[8], V1[8];
                #pragma unroll
                for (int q2 = 0; q2 < 4; q2++) {
                    const uint32_t off = bBaseOff + q2 * (16 * FROWB) + ks * 32;
                    ldsm_x4(V0[q2*2], V1[q2*2], V0[q2*2+1], V1[q2*2+1], vb + off);
                }
                #pragma unroll
                for (int nt = 0; nt < 8; nt++) {
                    float* c = O[nt];
                    mma16816(c[0], c[1], c[2], c[3],
                             pa[0], pa[1], pa[2], pa[3], V0[nt], V1[nt]);
                }
            }
        }
        if (n + 2 < nkv) pref_kv(n + 2);
        asm volatile("cp.async.commit_group;" ::: "memory");
    }

    lA += __shfl_xor_sync(0xffffffffu, lA, 1);
    lA += __shfl_xor_sync(0xffffffffu, lA, 2);
    lB += __shfl_xor_sync(0xffffffffu, lB, 1);
    lB += __shfl_xor_sync(0xffffffffu, lB, 2);

    const float iA = 1.f / lA, iB = 1.f / lB;
    #pragma unroll
    for (int nt = 0; nt < 8; nt++) {
        const size_t d0 = (size_t)h * 64 + nt * 8 + qk;
        store_h2(y16, ((size_t)b * TT + row0) * CC + d0, O[nt][0] * iA, O[nt][1] * iA);
        store_h2(y16, ((size_t)b * TT + row1) * CC + d0, O[nt][2] * iB, O[nt][3] * iB);
    }
}

// ---------------- launch ---------------------------------------------------
extern "C" void kernel_launch(void* const* d_in, const int* in_sizes, int n_in,
                              void* d_out, int out_size)
{
    const float* x   = (const float*)d_in[0];
    const float* Wq  = (const float*)d_in[1];
    const float* Wkv = (const float*)d_in[2];
    const float* Wc  = (const float*)d_in[3];
    float* out = (float*)d_out;

    float *gc, *gs;
    __half *x16, *y16, *q16, *k16, *vt16, *wh, *wch;
    cudaGetSymbolAddress((void**)&gc, g_cos);
    cudaGetSymbolAddress((void**)&gs, g_sin);
    cudaGetSymbolAddress((void**)&x16, g_x16);
    cudaGetSymbolAddress((void**)&y16, g_y16);
    cudaGetSymbolAddress((void**)&q16, g_q16);
    cudaGetSymbolAddress((void**)&k16, g_k16);
    cudaGetSymbolAddress((void**)&vt16, g_vt16);
    cudaGetSymbolAddress((void**)&wh, g_wh);
    cudaGetSymbolAddress((void**)&wch, g_wch);

    cudaFuncSetAttribute(gemm_kernel_mma, cudaFuncAttributeMaxDynamicSharedMemorySize, SMEM_DYN);
    cudaFuncSetAttribute(flash_mma_kernel, cudaFuncAttributeMaxDynamicSharedMemorySize, FSMEM);

    // #0: x -> fp16
    {
        int n4 = MM * GK / 4;
        split_kernel<<<(n4 + 255) / 256, 256>>>((const float4*)x, (uint2*)x16, n4);
    }
    // #1: weight transposes (single fp16) + rope table
    transpose_split_all<<<dim3(128, GK / 32 + 1), dim3(32, 8)>>>(
        Wq, Wkv, Wc, wh, wch, gc, gs);

    // #2: fused QKV GEMM
    gemm_kernel_mma<<<dim3(3 * CC / 128, MM / 128), 256, SMEM_DYN>>>(
        x16, wh, nullptr, 3 * CC, 1, gc, gs, q16, k16, vt16);

    // #3: attention (ncu target)
    flash_mma_kernel<<<dim3(TT / 128, HH, BB), 256, FSMEM>>>(q16, k16, vt16, y16);

    // #4: out = y @ Wc
    gemm_kernel_mma<<<dim3(CC / 128, MM / 128), 256, SMEM_DYN>>>(
        y16, wch, out, CC, 0, nullptr, nullptr, nullptr, nullptr, nullptr);
}

// round 15
// speedup vs baseline: 1.0497x; 1.0497x over previous
#include <cuda_runtime.h>
#include <cuda_fp16.h>
#include <math.h>
#include <stdint.h>

#define BB 4
#define TT 2048
#define HH 16
#define DD 64
#define CC (HH*DD)      // 1024
#define MM (BB*TT)      // 8192
#define GK 1024         // K of all GEMMs

// ---------------- scratch (device globals; no allocation allowed) ----------
__device__ __align__(256) float g_cos[TT * 32];
__device__ __align__(256) float g_sin[TT * 32];

__device__ __align__(256) __half g_x16[(size_t)MM * GK];
__device__ __align__(256) __half g_y16[(size_t)MM * GK];
__device__ __align__(256) __half g_q16[(size_t)BB*HH*TT*DD];
__device__ __align__(256) __half g_k16[(size_t)BB*HH*TT*DD];
__device__ __align__(256) __half g_vt16[(size_t)BB*HH*TT*DD];
// weights transposed [N,K], single fp16
__device__ __align__(256) __half g_wh[(size_t)3 * CC * GK];
__device__ __align__(256) __half g_wch[(size_t)CC * GK];

// ---------------- helpers ----------------------------------------------------
__device__ __forceinline__ uint32_t smem_u32(const void* p) {
    return (uint32_t)__cvta_generic_to_shared(p);
}

__device__ __forceinline__ void cp_async16(uint32_t saddr, const void* gaddr) {
    asm volatile("cp.async.cg.shared.global [%0], [%1], 16;" :: "r"(saddr), "l"(gaddr) : "memory");
}

__device__ __forceinline__ void ldsm_x4(uint32_t& r0, uint32_t& r1, uint32_t& r2, uint32_t& r3,
                                        uint32_t addr) {
    asm volatile("ldmatrix.sync.aligned.m8n8.x4.shared.b16 {%0,%1,%2,%3}, [%4];"
                 : "=r"(r0), "=r"(r1), "=r"(r2), "=r"(r3) : "r"(addr));
}

__device__ __forceinline__ void mma16816(float& c0, float& c1, float& c2, float& c3,
                                         uint32_t a0, uint32_t a1, uint32_t a2, uint32_t a3,
                                         uint32_t b0, uint32_t b1) {
    asm volatile(
        "mma.sync.aligned.m16n8k16.row.col.f32.f16.f16.f32 "
        "{%0,%1,%2,%3}, {%4,%5,%6,%7}, {%8,%9}, {%0,%1,%2,%3};"
        : "+f"(c0), "+f"(c1), "+f"(c2), "+f"(c3)
        : "r"(a0), "r"(a1), "r"(a2), "r"(a3), "r"(b0), "r"(b1));
}

__device__ __forceinline__ uint32_t pack_h16(float a, float b) {
    __half2 t = __floats2half2_rn(a, b);
    return *reinterpret_cast<uint32_t*>(&t);
}

__device__ __forceinline__ void store_h2(__half* dst, size_t off, float a, float b) {
    *reinterpret_cast<__half2*>(dst + off) = __floats2half2_rn(a, b);
}

// ---------------- HMMA GEMM: C = A16 @ B16^T (single fp16) -----------------
// 128x128 CTA tile, 8 warps (2m x 4n), warp tile 64x32, BK=64, 3-stage
// cp.async pipeline, ONE barrier per k-chunk, 128B rows w/ j^(r&7) swizzle,
// 2 CTAs/SM.
#define BK 64
#define NUMK (GK / BK)          // 16
#define ROWB 128                // 128B data (64 fp16), swizzled
#define TILE_B (128 * ROWB)     // 16384
#define STAGE_B (2 * TILE_B)    // 32768 (A, B)
#define SMEM_DYN (3 * STAGE_B)  // 98304 -> 2 CTAs/SM

__global__ void __launch_bounds__(256, 2)
gemm_kernel_mma(const __half* __restrict__ A16, const __half* __restrict__ B16,
                float* __restrict__ Cm, int Ndim, int mode,
                const float* __restrict__ gcos, const float* __restrict__ gsin,
                __half* __restrict__ q16, __half* __restrict__ k16,
                __half* __restrict__ vt16)
{
    extern __shared__ char smem_raw[];
    const uint32_t sbase = smem_u32(smem_raw);

    const int tid  = threadIdx.x;
    const int lane = tid & 31;
    const int warp = tid >> 5;
    const int mw   = warp & 1;
    const int nw   = warp >> 1;
    const int m0 = blockIdx.y * 128;
    const int n0 = blockIdx.x * 128;

    auto prefetch = [&](int kc) {
        const uint32_t sstage = sbase + (uint32_t)(kc % 3) * STAGE_B;
        #pragma unroll
        for (int i = 0; i < 8; i++) {
            const int c = i * 256 + tid;        // 0..2047
            const int tile = c >> 10;           // 0=A 1=B
            const int r = (c >> 3) & 127;
            const int j = c & 7;
            const __half* g = (tile == 0)
                ? A16 + (size_t)(m0 + r) * GK + kc * BK + j * 8
                : B16 + (size_t)(n0 + r) * GK + kc * BK + j * 8;
            cp_async16(sstage + tile * TILE_B + r * ROWB + ((j ^ (r & 7)) << 4), g);
        }
    };

    prefetch(0);
    asm volatile("cp.async.commit_group;" ::: "memory");
    prefetch(1);
    asm volatile("cp.async.commit_group;" ::: "memory");

    const uint32_t aRowBase = (uint32_t)((mw * 64 + (lane & 15)) * ROWB);
    const uint32_t xa = (lane & 15) & 7;
    const uint32_t bRowBase = (uint32_t)((nw * 32 + (lane & 7) + ((lane >> 4) << 3)) * ROWB);
    const uint32_t xb = lane & 7;
    const uint32_t aHalf = (lane >> 4);
    const uint32_t bHalf = ((lane >> 3) & 1);

    float acc[4][4][4];
    #pragma unroll
    for (int mt = 0; mt < 4; mt++)
        #pragma unroll
        for (int nt = 0; nt < 4; nt++)
            #pragma unroll
            for (int e = 0; e < 4; e++) acc[mt][nt][e] = 0.f;

    for (int kc = 0; kc < NUMK; kc++) {
        asm volatile("cp.async.wait_group 1;" ::: "memory");
        __syncthreads();

        const uint32_t sstage = sbase + (uint32_t)(kc % 3) * STAGE_B;
        const uint32_t aTile = sstage;
        const uint32_t bTile = sstage + TILE_B;

        #pragma unroll
        for (int ks = 0; ks < 4; ks++) {
            const uint32_t aOff = ((uint32_t)(ks * 2 + aHalf) ^ xa) << 4;
            const uint32_t bOff = ((uint32_t)(ks * 2 + bHalf) ^ xb) << 4;
            uint32_t bh[4][2];
            #pragma unroll
            for (int np = 0; np < 2; np++) {
                const uint32_t off = bRowBase + np * (16 * ROWB) + bOff;
                ldsm_x4(bh[np*2][0], bh[np*2][1], bh[np*2+1][0], bh[np*2+1][1], bTile + off);
            }
            #pragma unroll
            for (int mt = 0; mt < 4; mt++) {
                uint32_t ah[4];
                const uint32_t off = aRowBase + mt * (16 * ROWB) + aOff;
                ldsm_x4(ah[0], ah[1], ah[2], ah[3], aTile + off);
                #pragma unroll
                for (int nt = 0; nt < 4; nt++) {
                    float* c = acc[mt][nt];
                    mma16816(c[0], c[1], c[2], c[3],
                             ah[0], ah[1], ah[2], ah[3], bh[nt][0], bh[nt][1]);
                }
            }
        }
        if (kc + 2 < NUMK) prefetch(kc + 2);
        asm volatile("cp.async.commit_group;" ::: "memory");
    }

    if (mode == 0) {
        const int rbase = m0 + mw * 64 + (lane >> 2);
        const int cbase = n0 + nw * 32 + ((lane & 3) << 1);
        #pragma unroll
        for (int mt = 0; mt < 4; mt++) {
            #pragma unroll
            for (int nt = 0; nt < 4; nt++) {
                float* c = acc[mt][nt];
                float* p0 = Cm + (size_t)(rbase + mt * 16) * Ndim + cbase + nt * 8;
                float* p1 = p0 + (size_t)8 * Ndim;
                *reinterpret_cast<float2*>(p0) = make_float2(c[0], c[1]);
                *reinterpret_cast<float2*>(p1) = make_float2(c[2], c[3]);
            }
        }
        return;
    }

    // ---- fused QKV epilogue: stage fp32 tile in smem [128][132] ----
    float* sm = reinterpret_cast<float*>(smem_raw);
    __syncthreads();
    const int rloc = mw * 64 + (lane >> 2);
    const int cloc = nw * 32 + ((lane & 3) << 1);
    #pragma unroll
    for (int mt = 0; mt < 4; mt++) {
        #pragma unroll
        for (int nt = 0; nt < 4; nt++) {
            float* c = acc[mt][nt];
            float* p0 = sm + (size_t)(rloc + mt * 16) * 132 + cloc + nt * 8;
            *reinterpret_cast<float2*>(p0)           = make_float2(c[0], c[1]);
            *reinterpret_cast<float2*>(p0 + 8 * 132) = make_float2(c[2], c[3]);
        }
    }
    __syncthreads();

    const int ct = blockIdx.x;
    const int b = m0 >> 11;
    const int t_base = m0 & (TT - 1);

    if (ct < 16) {
        const bool isQ = (ct < 8);
        // Q scale folds 1/sqrt(D) AND log2(e): flash softmax runs in exp2 domain
        const float qs = isQ ? (0.125f * 1.4426950408889634f) : 1.0f;
        __half* dst = isQ ? q16 : k16;
        const int hbase = (isQ ? ct : (ct - 8)) * 2;
        #pragma unroll
        for (int i = 0; i < 16; i++) {
            const int idx = i * 256 + tid;
            const int dp = (idx & 15) * 2;
            const int hs = (idx >> 4) & 1;
            const int r  = idx >> 5;
            const int t  = t_base + r;
            const float c0 = gcos[t * 32 + dp],  c1 = gcos[t * 32 + dp + 1];
            const float s0 = gsin[t * 32 + dp],  s1 = gsin[t * 32 + dp + 1];
            const float* row = sm + (size_t)r * 132 + hs * 64;
            const float x1 = row[dp],      x1b = row[dp + 1];
            const float x2 = row[dp + 32], x2b = row[dp + 33];
            const float o0 = (x1 * c0 - x2 * s0) * qs;
            const float o1 = (x1b * c1 - x2b * s1) * qs;
            const float o2 = (x2 * c0 + x1 * s0) * qs;
            const float o3 = (x2b * c1 + x1b * s1) * qs;
            const size_t base = (((size_t)b * HH + hbase + hs) * TT + t) * 64;
            store_h2(dst, base + dp, o0, o1);
            store_h2(dst, base + dp + 32, o2, o3);
        }
    } else {
        const int hbase = (ct - 16) * 2;
        #pragma unroll
        for (int i = 0; i < 32; i++) {
            const int idx = i * 256 + tid;
            const int c  = idx >> 6;
            const int t2 = idx & 63;
            const int hs = c >> 6;
            const int d  = c & 63;
            const float a  = sm[(size_t)(2 * t2) * 132 + c];
            const float bv = sm[(size_t)(2 * t2 + 1) * 132 + c];
            const int t = t_base + 2 * t2;
            store_h2(vt16, (((size_t)b * HH + hbase + hs) * 64 + d) * TT + t, a, bv);
        }
    }
}

// ---------------- fp32 -> fp16 convert -------------------------------------
__global__ void split_kernel(const float4* __restrict__ in, uint2* __restrict__ out, int n4)
{
    int i = blockIdx.x * blockDim.x + threadIdx.x;
    if (i >= n4) return;
    float4 v = in[i];
    __half2 a = __floats2half2_rn(v.x, v.y);
    __half2 b = __floats2half2_rn(v.z, v.w);
    uint2 o;
    o.x = *reinterpret_cast<uint32_t*>(&a);
    o.y = *reinterpret_cast<uint32_t*>(&b);
    out[i] = o;
}

// -------- combined W transpose (single fp16) + RoPE table ------------------
__global__ void transpose_split_all(const float* __restrict__ Wq,
                                    const float* __restrict__ Wkv,
                                    const float* __restrict__ Wc,
                                    __half* __restrict__ wh, __half* __restrict__ wch,
                                    float* __restrict__ gcos, float* __restrict__ gsin)
{
    const int tx = threadIdx.x, ty = threadIdx.y;
    if (blockIdx.y == 32) {
        const int tid = ty * 32 + tx;
        #pragma unroll
        for (int e = 0; e < 2; e++) {
            int i = blockIdx.x * 512 + e * 256 + tid;
            int t = i >> 5;
            int d = i & 31;
            float inv = (float)exp(-((double)(2 * d) / 64.0) * log(10000.0));
            float ang = (float)t * inv;
            gcos[i] = cosf(ang);
            gsin[i] = sinf(ang);
        }
        return;
    }

    __shared__ float t[32][33];
    const int nx = blockIdx.x;
    const int k0 = blockIdx.y * 32;
    const float* W;
    __half* Th;
    int N, n0;
    if (nx < 32)       { W = Wq;  N = CC;     n0 = nx * 32;        Th = wh; }
    else if (nx < 96)  { W = Wkv; N = 2 * CC; n0 = (nx - 32) * 32;
                         Th = wh + (size_t)CC * GK; }
    else               { W = Wc;  N = CC;     n0 = (nx - 96) * 32; Th = wch; }

    #pragma unroll
    for (int i = 0; i < 32; i += 8)
        t[ty + i][tx] = W[(size_t)(k0 + ty + i) * N + n0 + tx];
    __syncthreads();
    #pragma unroll
    for (int i = 0; i < 32; i += 8) {
        float v = t[tx][ty + i];
        Th[(size_t)(n0 + ty + i) * GK + k0 + tx] = __float2half_rn(v);
    }
}

// ---------------- Flash attention, fp16 HMMA, exp2-domain softmax ----------
// (R13 form: unconditional fragment loads/MMAs — branchy skips regressed)
#define FROWB 144
#define FQ_TILE (128 * FROWB)        // 18432
#define FK_TILE (64 * FROWB)         // 9216
#define FV_TILE (64 * FROWB)         // 9216
#define FSTAGE (FK_TILE + FV_TILE)   // 18432
#define FSMEM (FQ_TILE + 3 * FSTAGE) // 73728 -> 2 CTAs/SM

__global__ void __launch_bounds__(256, 2)
flash_mma_kernel(const __half* __restrict__ q16, const __half* __restrict__ k16,
                 const __half* __restrict__ vt16, __half* __restrict__ y16)
{
    extern __shared__ char smem_raw[];
    const uint32_t sQ  = smem_u32(smem_raw);
    const uint32_t sKV = sQ + FQ_TILE;

    const int tid = threadIdx.x, lane = tid & 31, warp = tid >> 5;
    const int t0 = (gridDim.x - 1 - blockIdx.x) * 128;   // heavy-first
    const int h = blockIdx.y, b = blockIdx.z;
    const size_t bh = (size_t)b * HH + h;
    const int nkv = t0 / 64 + 2;

    #pragma unroll
    for (int i = 0; i < 4; i++) {
        int idx = i * 256 + tid;
        int r = idx >> 3, j = idx & 7;
        cp_async16(sQ + r * FROWB + j * 16, q16 + (bh * TT + t0 + r) * 64 + j * 8);
    }
    auto pref_kv = [&](int n) {
        const uint32_t sb = sKV + (uint32_t)(n % 3) * FSTAGE;
        const int j0 = n * 64;
        #pragma unroll
        for (int i = 0; i < 4; i++) {
            int idx = i * 256 + tid;
            int arr = idx >> 9, r = (idx >> 3) & 63, j = idx & 7;
            const __half* g = arr ? (vt16 + (bh * 64 + r) * TT + j0 + j * 8)
                                  : (k16 + (bh * TT + j0 + r) * 64 + j * 8);
            cp_async16(sb + arr * FK_TILE + r * FROWB + j * 16, g);
        }
    };
    pref_kv(0);
    asm volatile("cp.async.commit_group;" ::: "memory");
    pref_kv(1);
    asm volatile("cp.async.commit_group;" ::: "memory");

    const int wrow = t0 + warp * 16;
    const int gr = lane >> 2;
    const int qk = (lane & 3) * 2;
    const int row0 = wrow + gr;
    const int row1 = row0 + 8;

    uint32_t qa[4][4];
    float O[8][4];
    #pragma unroll
    for (int nt = 0; nt < 8; nt++)
        #pragma unroll
        for (int e = 0; e < 4; e++) O[nt][e] = 0.f;
    float mA = -1e30f, mB = -1e30f, lA = 0.f, lB = 0.f;

    const uint32_t bBaseOff = ((lane & 7) + ((lane >> 4) << 3)) * FROWB + (((lane >> 3) & 1) << 4);

    for (int n = 0; n < nkv; n++) {
        asm volatile("cp.async.wait_group 1;" ::: "memory");
        __syncthreads();

        if (n == 0) {
            const uint32_t qb = sQ + (warp * 16 + (lane & 15)) * FROWB + ((lane >> 4) << 4);
            #pragma unroll
            for (int ks = 0; ks < 4; ks++)
                ldsm_x4(qa[ks][0], qa[ks][1], qa[ks][2], qa[ks][3], qb + ks * 32);
        }

        const int j0 = n * 64;
        if (j0 <= wrow + 15) {
            const uint32_t sb = sKV + (uint32_t)(n % 3) * FSTAGE;
            float S[8][4];
            #pragma unroll
            for (int nt = 0; nt < 8; nt++)
                #pragma unroll
                for (int e = 0; e < 4; e++) S[nt][e] = 0.f;

            #pragma unroll
            for (int ks = 0; ks < 4; ks++) {
                uint32_t B0[8], B1[8];
                #pragma unroll
                for (int q2 = 0; q2 < 4; q2++) {
                    const uint32_t off = bBaseOff + q2 * (16 * FROWB) + ks * 32;
                    ldsm_x4(B0[q2*2], B1[q2*2], B0[q2*2+1], B1[q2*2+1], sb + off);
                }
                #pragma unroll
                for (int nt = 0; nt < 8; nt++) {
                    float* c = S[nt];
                    mma16816(c[0], c[1], c[2], c[3],
                             qa[ks][0], qa[ks][1], qa[ks][2], qa[ks][3], B0[nt], B1[nt]);
                }
            }

            if (j0 + 63 > wrow) {
                #pragma unroll
                for (int nt = 0; nt < 8; nt++) {
                    const int c0 = j0 + nt * 8 + qk;
                    if (c0 > row0)     S[nt][0] = -1e30f;
                    if (c0 + 1 > row0) S[nt][1] = -1e30f;
                    if (c0 > row1)     S[nt][2] = -1e30f;
                    if (c0 + 1 > row1) S[nt][3] = -1e30f;
                }
            }

            float tmA = -1e30f, tmB = -1e30f;
            #pragma unroll
            for (int nt = 0; nt < 8; nt++) {
                tmA = fmaxf(tmA, fmaxf(S[nt][0], S[nt][1]));
                tmB = fmaxf(tmB, fmaxf(S[nt][2], S[nt][3]));
            }
            tmA = fmaxf(tmA, __shfl_xor_sync(0xffffffffu, tmA, 1));
            tmA = fmaxf(tmA, __shfl_xor_sync(0xffffffffu, tmA, 2));
            tmB = fmaxf(tmB, __shfl_xor_sync(0xffffffffu, tmB, 1));
            tmB = fmaxf(tmB, __shfl_xor_sync(0xffffffffu, tmB, 2));

            if (__any_sync(0xffffffffu, (tmA > mA) || (tmB > mB))) {
                const float mnA = fmaxf(mA, tmA), mnB = fmaxf(mB, tmB);
                const float aA = exp2f(mA - mnA), aB = exp2f(mB - mnB);
                lA *= aA; lB *= aB;
                #pragma unroll
                for (int nt = 0; nt < 8; nt++) {
                    O[nt][0] *= aA; O[nt][1] *= aA;
                    O[nt][2] *= aB; O[nt][3] *= aB;
                }
                mA = mnA; mB = mnB;
            }

            float sumA = 0.f, sumB = 0.f;
            #pragma unroll
            for (int nt = 0; nt < 8; nt++) {
                S[nt][0] = exp2f(S[nt][0] - mA);
                S[nt][1] = exp2f(S[nt][1] - mA);
                S[nt][2] = exp2f(S[nt][2] - mB);
                S[nt][3] = exp2f(S[nt][3] - mB);
                sumA += S[nt][0] + S[nt][1];
                sumB += S[nt][2] + S[nt][3];
            }
            lA += sumA;
            lB += sumB;

            const uint32_t vb = sb + FK_TILE;
            #pragma unroll
            for (int ks = 0; ks < 4; ks++) {
                const int n0t = 2 * ks, n1t = 2 * ks + 1;
                uint32_t pa[4];
                pa[0] = pack_h16(S[n0t][0], S[n0t][1]);
                pa[1] = pack_h16(S[n0t][2], S[n0t][3]);
                pa[2] = pack_h16(S[n1t][0], S[n1t][1]);
                pa[3] = pack_h16(S[n1t][2], S[n1t][3]);
                uint32_t V0[8], V1[8];
                #pragma unroll
                for (int q2 = 0; q2 < 4; q2++) {
                    const uint32_t off = bBaseOff + q2 * (16 * FROWB) + ks * 32;
                    ldsm_x4(V0[q2*2], V1[q2*2], V0[q2*2+1], V1[q2*2+1], vb + off);
                }
                #pragma unroll
                for (int nt = 0; nt < 8; nt++) {
                    float* c = O[nt];
                    mma16816(c[0], c[1], c[2], c[3],
                             pa[0], pa[1], pa[2], pa[3], V0[nt], V1[nt]);
                }
            }
        }
        if (n + 2 < nkv) pref_kv(n + 2);
        asm volatile("cp.async.commit_group;" ::: "memory");
    }

    lA += __shfl_xor_sync(0xffffffffu, lA, 1);
    lA += __shfl_xor_sync(0xffffffffu, lA, 2);
    lB += __shfl_xor_sync(0xffffffffu, lB, 1);
    lB += __shfl_xor_sync(0xffffffffu, lB, 2);

    const float iA = 1.f / lA, iB = 1.f / lB;
    #pragma unroll
    for (int nt = 0; nt < 8; nt++) {
        const size_t d0 = (size_t)h * 64 + nt * 8 + qk;
        store_h2(y16, ((size_t)b * TT + row0) * CC + d0, O[nt][0] * iA, O[nt][1] * iA);
        store_h2(y16, ((size_t)b * TT + row1) * CC + d0, O[nt][2] * iB, O[nt][3] * iB);
    }
}

// ---------------- launch ---------------------------------------------------
extern "C" void kernel_launch(void* const* d_in, const int* in_sizes, int n_in,
                              void* d_out, int out_size)
{
    const float* x   = (const float*)d_in[0];
    const float* Wq  = (const float*)d_in[1];
    const float* Wkv = (const float*)d_in[2];
    const float* Wc  = (const float*)d_in[3];
    float* out = (float*)d_out;

    float *gc, *gs;
    __half *x16, *y16, *q16, *k16, *vt16, *wh, *wch;
    cudaGetSymbolAddress((void**)&gc, g_cos);
    cudaGetSymbolAddress((void**)&gs, g_sin);
    cudaGetSymbolAddress((void**)&x16, g_x16);
    cudaGetSymbolAddress((void**)&y16, g_y16);
    cudaGetSymbolAddress((void**)&q16, g_q16);
    cudaGetSymbolAddress((void**)&k16, g_k16);
    cudaGetSymbolAddress((void**)&vt16, g_vt16);
    cudaGetSymbolAddress((void**)&wh, g_wh);
    cudaGetSymbolAddress((void**)&wch, g_wch);

    cudaFuncSetAttribute(gemm_kernel_mma, cudaFuncAttributeMaxDynamicSharedMemorySize, SMEM_DYN);
    cudaFuncSetAttribute(flash_mma_kernel, cudaFuncAttributeMaxDynamicSharedMemorySize, FSMEM);

    // #0: x -> fp16
    {
        int n4 = MM * GK / 4;
        split_kernel<<<(n4 + 255) / 256, 256>>>((const float4*)x, (uint2*)x16, n4);
    }
    // #1: weight transposes (single fp16) + rope table
    transpose_split_all<<<dim3(128, GK / 32 + 1), dim3(32, 8)>>>(
        Wq, Wkv, Wc, wh, wch, gc, gs);

    // #2: fused QKV GEMM
    gemm_kernel_mma<<<dim3(3 * CC / 128, MM / 128), 256, SMEM_DYN>>>(
        x16, wh, nullptr, 3 * CC, 1, gc, gs, q16, k16, vt16);

    // #3: attention (ncu target)
    flash_mma_kernel<<<dim3(TT / 128, HH, BB), 256, FSMEM>>>(q16, k16, vt16, y16);

    // #4: out = y @ Wc
    gemm_kernel_mma<<<dim3(CC / 128, MM / 128), 256, SMEM_DYN>>>(
        y16, wch, out, CC, 0, nullptr, nullptr, nullptr, nullptr, nullptr);
}